// round 17
// baseline (speedup 1.0000x reference)
#include <cuda_runtime.h>
#include <cuda_fp16.h>
#include <math.h>
#include <stdint.h>

#define NN    50000
#define FH    128      // H*C
#define NH    4
#define EMAX  800000
#define NEG   0.2f
#define NBMAX 256      // >= ceil(NN/256) scan blocks
#define LOG2E 1.44269504088896f

// ---------------- scratch (static device globals; no runtime alloc) --------
__device__ __half g_xph[NN * FH];        // projected features fp16 [N][128]
__device__ float  g_asrc[NN * NH];       // prescaled by log2e
__device__ float  g_adst[NN * NH];       // prescaled by log2e
__device__ int    g_deg[NN];             // real-edge counts; re-zeroed in scan
__device__ int    g_ord[EMAX];           // per-edge ordinal within its dst row
__device__ int    g_rowptr[NN + 1];
__device__ int    g_bval[NBMAX];
__device__ volatile int g_bflag[NBMAX];
__device__ int    g_hdone;               // hist phase counter; reset by k_agg
__device__ uint4  g_rec[EMAX + NN];      // per-slot record {src, w01(h2), w23(h2), pad}

// ---------------- helpers ---------------------------------------------------
__device__ __forceinline__ void mma_f16(float* c, const uint32_t* a,
                                        uint32_t b0, uint32_t b1) {
    asm volatile(
        "mma.sync.aligned.m16n8k16.row.col.f32.f16.f16.f32 "
        "{%0,%1,%2,%3}, {%4,%5,%6,%7}, {%8,%9}, {%0,%1,%2,%3};"
        : "+f"(c[0]), "+f"(c[1]), "+f"(c[2]), "+f"(c[3])
        : "r"(a[0]), "r"(a[1]), "r"(a[2]), "r"(a[3]), "r"(b0), "r"(b1));
}

__device__ __forceinline__ float ex2(float a) {
    float r;
    asm("ex2.approx.f32 %0, %1;" : "=f"(r) : "f"(a));
    return r;
}

__device__ __forceinline__ float lrelu(float a) { return fmaxf(a, NEG * a); }

// ---------------- k_att: a_src/a_dst directly from x ------------------------
__global__ __launch_bounds__(256) void k_att(
    const float* __restrict__ x, const float* __restrict__ W,
    const float* __restrict__ attS, const float* __restrict__ attD, int n)
{
    __shared__ float sv[8][128];   // vec 0-3: S heads, 4-7: D heads
    __shared__ float sa[256];      // attS||attD, prescaled by log2e
    int t = threadIdx.x;
    sa[t] = (t < 128 ? attS[t] : attD[t - 128]) * LOG2E;
    __syncthreads();

    for (int j = t; j < 8 * 128; j += 256) {
        int v = j >> 7, k = j & 127;
        int h = v & 3;
        const float* wp = W + (h * 32) * 128 + k;
        const float* ap = sa + (v >> 2) * 128 + h * 32;
        float s = 0.f;
#pragma unroll
        for (int c = 0; c < 32; c++) s += wp[c * 128] * ap[c];
        sv[v][k] = s;
    }
    __syncthreads();

    int i = blockIdx.x * 256 + t;
    if (i >= n) return;
    const float4* xr = (const float4*)(x + (size_t)i * 128);
    float r[8] = {0.f, 0.f, 0.f, 0.f, 0.f, 0.f, 0.f, 0.f};
#pragma unroll 4
    for (int q = 0; q < 32; q++) {
        float4 v = xr[q];
#pragma unroll
        for (int vv = 0; vv < 8; vv++) {
            float4 s4 = *(const float4*)&sv[vv][q * 4];
            r[vv] += v.x * s4.x + v.y * s4.y + v.z * s4.z + v.w * s4.w;
        }
    }
    *(float4*)(g_asrc + i * 4) = make_float4(r[0], r[1], r[2], r[3]);
    *(float4*)(g_adst + i * 4) = make_float4(r[4], r[5], r[6], r[7]);
}

// ---------------- GEMM: xp = x @ W^T via fp16 m16n8k16, fp16 output ---------
#define XPH 24    // smem pitch in halves
__global__ __launch_bounds__(512) void k_gemm(
    const float* __restrict__ x, const float* __restrict__ W, int n)
{
    __shared__ __half xsh[128 * XPH];
    __shared__ __half wsh[128 * XPH];

    int t = threadIdx.x;
    int row0 = blockIdx.x * 128;
    int wid = t >> 5, lane = t & 31;
    int wm = wid >> 2, wn = wid & 3;
    int g = lane >> 2, q4 = lane & 3;

    float acc[2][4][4];
#pragma unroll
    for (int mt = 0; mt < 2; mt++)
#pragma unroll
        for (int nt = 0; nt < 4; nt++)
#pragma unroll
            for (int c = 0; c < 4; c++) acc[mt][nt][c] = 0.f;

    for (int kc = 0; kc < 128; kc += 16) {
        {
            int r = t >> 2, q = t & 3;
            float4 v = make_float4(0.f, 0.f, 0.f, 0.f);
            if (row0 + r < n) v = *(const float4*)(x + (size_t)(row0 + r) * 128 + kc + q * 4);
            __half2* p = (__half2*)(xsh + r * XPH + q * 4);
            p[0] = __floats2half2_rn(v.x, v.y);
            p[1] = __floats2half2_rn(v.z, v.w);
        }
        {
            int oc = t >> 2, q = t & 3;
            float4 v = *(const float4*)(W + (size_t)oc * 128 + kc + q * 4);
            __half2* p = (__half2*)(wsh + oc * XPH + q * 4);
            p[0] = __floats2half2_rn(v.x, v.y);
            p[1] = __floats2half2_rn(v.z, v.w);
        }
        __syncthreads();

        uint32_t a[2][4];
#pragma unroll
        for (int mt = 0; mt < 2; mt++) {
            const __half* base = xsh + (wm * 32 + mt * 16 + g) * XPH + 2 * q4;
            a[mt][0] = *(const uint32_t*)(base);
            a[mt][1] = *(const uint32_t*)(base + 8 * XPH);
            a[mt][2] = *(const uint32_t*)(base + 8);
            a[mt][3] = *(const uint32_t*)(base + 8 * XPH + 8);
        }
#pragma unroll
        for (int nt = 0; nt < 4; nt++) {
            const __half* bb = wsh + (wn * 32 + nt * 8 + g) * XPH + 2 * q4;
            uint32_t b0 = *(const uint32_t*)(bb);
            uint32_t b1 = *(const uint32_t*)(bb + 8);
#pragma unroll
            for (int mt = 0; mt < 2; mt++)
                mma_f16(acc[mt][nt], a[mt], b0, b1);
        }
        __syncthreads();
    }

#pragma unroll
    for (int mt = 0; mt < 2; mt++) {
#pragma unroll
        for (int half = 0; half < 2; half++) {
            int r = row0 + wm * 32 + mt * 16 + half * 8 + g;
            if (r < n) {
#pragma unroll
                for (int nt = 0; nt < 4; nt++) {
                    int cbase = wn * 32 + nt * 8 + q4 * 2;
                    *(__half2*)(g_xph + (size_t)r * 128 + cbase) =
                        __floats2half2_rn(acc[mt][nt][half * 2 + 0],
                                          acc[mt][nt][half * 2 + 1]);
                }
            }
        }
    }
}

// ---------------- fused hist + scan -----------------------------------------
__global__ __launch_bounds__(256) void k_hs(
    const int* __restrict__ dst, int n, int E, int nhist, int nscan)
{
    __shared__ int s[256];
    int t = threadIdx.x, b = blockIdx.x;

    if (b < nhist) {
        if (b == 0 && t < NBMAX) g_bflag[t] = 0;
        int e = b * 256 + t;
        if (e < E) {
            int d = __ldcs(dst + e);
            g_ord[e] = atomicAdd(&g_deg[d], 1);
        }
        __syncthreads();
        if (t == 0) { __threadfence(); atomicAdd(&g_hdone, 1); }
        return;
    }

    if (t == 0) {
        while (*(volatile int*)&g_hdone < nhist) { }
        __threadfence();
    }
    __syncthreads();

    int sb = b - nhist;
    int i = sb * 256 + t;
    int v = 0;
    if (i < n) { v = g_deg[i] + 1; g_deg[i] = 0; }
    s[t] = v;
    __syncthreads();
#pragma unroll
    for (int off = 1; off < 256; off <<= 1) {
        int u = (t >= off) ? s[t - off] : 0;
        __syncthreads();
        s[t] += u;
        __syncthreads();
    }
    int incl = s[t];
    int agg  = s[255];
    if (t == 255) {
        g_bval[sb] = agg;
        __threadfence();
        g_bflag[sb] = 1;
    }
    int part = 0;
    for (int j = t; j < sb; j += 256) {
        while (g_bflag[j] == 0) { }
        part += *(volatile int*)&g_bval[j];
    }
    __syncthreads();
    s[t] = part;
    __syncthreads();
#pragma unroll
    for (int off = 128; off > 0; off >>= 1) {
        if (t < off) s[t] += s[t + off];
        __syncthreads();
    }
    int excl0 = s[0];
    if (i < n) g_rowptr[i] = excl0 + incl - v;
    if (sb == nscan - 1 && t == 255) g_rowptr[n] = excl0 + agg;
}

// ---------------- scatter + weights -> ONE packed record per slot -----------
__global__ void k_scatw(const int* __restrict__ src, const int* __restrict__ dst,
                        int E, int n) {
    int e = blockIdx.x * blockDim.x + threadIdx.x;
    int total = E + n;
    if (e >= total) return;
    int sidx, didx, p;
    if (e < E) {
        sidx = __ldcs(src + e);
        didx = __ldcs(dst + e);
        p = g_rowptr[didx] + __ldcs(g_ord + e);
    } else {
        sidx = didx = e - E;
        p = g_rowptr[sidx + 1] - 1;          // self loop in last slot
    }
    float4 as = *(const float4*)(g_asrc + sidx * 4);
    float4 ad = *(const float4*)(g_adst + didx * 4);
    __half2 w01 = __floats2half2_rn(ex2(lrelu(as.x + ad.x)), ex2(lrelu(as.y + ad.y)));
    __half2 w23 = __floats2half2_rn(ex2(lrelu(as.z + ad.z)), ex2(lrelu(as.w + ad.w)));
    uint4 rec;
    rec.x = (unsigned)sidx;
    rec.y = *(uint32_t*)&w01;
    rec.z = *(uint32_t*)&w23;
    rec.w = 0u;
    g_rec[p] = rec;                           // single STG.128
}

// ---------------- aggregation: one warp per destination node ----------------
// One broadcast LDG.128 per edge carries src + all 4 head weights.
__global__ __launch_bounds__(256) void k_agg(
    const float* __restrict__ bias, float* __restrict__ out, int n)
{
    if (blockIdx.x == 0 && threadIdx.x == 0) g_hdone = 0;   // reset for replay

    int warp = (blockIdx.x * blockDim.x + threadIdx.x) >> 5;
    int lane = threadIdx.x & 31;
    if (warp >= n) return;
    int nd = warp;
    int h = lane >> 3;

    int begin = g_rowptr[nd], end = g_rowptr[nd + 1];

    float ax = 0.f, ay = 0.f, az = 0.f, aw = 0.f;
    float den = 0.f;
    const __half* xpb = g_xph + lane * 4;

#define EDGE_W(r)                                                          \
    ({ float2 f01 = __half22float2(*(__half2*)&(r).y);                     \
       float2 f23 = __half22float2(*(__half2*)&(r).z);                     \
       (h == 0) ? f01.x : (h == 1) ? f01.y : (h == 2) ? f23.x : f23.y; })

    int i = begin;
    for (; i + 4 <= end; i += 4) {
        uint4 r0 = g_rec[i], r1 = g_rec[i + 1], r2 = g_rec[i + 2], r3 = g_rec[i + 3];
        uint2 u0 = *(const uint2*)(xpb + (size_t)r0.x * 128);
        uint2 u1 = *(const uint2*)(xpb + (size_t)r1.x * 128);
        uint2 u2 = *(const uint2*)(xpb + (size_t)r2.x * 128);
        uint2 u3 = *(const uint2*)(xpb + (size_t)r3.x * 128);
        float w0 = EDGE_W(r0), w1 = EDGE_W(r1), w2 = EDGE_W(r2), w3 = EDGE_W(r3);
        float2 p0a = __half22float2(*(__half2*)&u0.x), p0b = __half22float2(*(__half2*)&u0.y);
        float2 p1a = __half22float2(*(__half2*)&u1.x), p1b = __half22float2(*(__half2*)&u1.y);
        float2 p2a = __half22float2(*(__half2*)&u2.x), p2b = __half22float2(*(__half2*)&u2.y);
        float2 p3a = __half22float2(*(__half2*)&u3.x), p3b = __half22float2(*(__half2*)&u3.y);
        ax = fmaf(w0, p0a.x, fmaf(w1, p1a.x, fmaf(w2, p2a.x, fmaf(w3, p3a.x, ax))));
        ay = fmaf(w0, p0a.y, fmaf(w1, p1a.y, fmaf(w2, p2a.y, fmaf(w3, p3a.y, ay))));
        az = fmaf(w0, p0b.x, fmaf(w1, p1b.x, fmaf(w2, p2b.x, fmaf(w3, p3b.x, az))));
        aw = fmaf(w0, p0b.y, fmaf(w1, p1b.y, fmaf(w2, p2b.y, fmaf(w3, p3b.y, aw))));
        den += (w0 + w1) + (w2 + w3);
    }
    for (; i < end; i++) {
        uint4 r0 = g_rec[i];
        uint2 u0 = *(const uint2*)(xpb + (size_t)r0.x * 128);
        float w0 = EDGE_W(r0);
        float2 pa = __half22float2(*(__half2*)&u0.x);
        float2 pb = __half22float2(*(__half2*)&u0.y);
        ax = fmaf(w0, pa.x, ax); ay = fmaf(w0, pa.y, ay);
        az = fmaf(w0, pb.x, az); aw = fmaf(w0, pb.y, aw);
        den += w0;
    }
#undef EDGE_W

    float inv = 1.0f / (den + 1e-16f);
    float4 bb = ((const float4*)bias)[lane];
    float4 o;
    o.x = ax * inv + bb.x;
    o.y = ay * inv + bb.y;
    o.z = az * inv + bb.z;
    o.w = aw * inv + bb.w;
    o.x = o.x > 0.f ? o.x : (__expf(o.x) - 1.f);
    o.y = o.y > 0.f ? o.y : (__expf(o.y) - 1.f);
    o.z = o.z > 0.f ? o.z : (__expf(o.z) - 1.f);
    o.w = o.w > 0.f ? o.w : (__expf(o.w) - 1.f);
    ((float4*)out)[(size_t)nd * 32 + lane] = o;
}

// ---------------- launch ----------------------------------------------------
extern "C" void kernel_launch(void* const* d_in, const int* in_sizes, int n_in,
                              void* d_out, int out_size)
{
    const float* x    = (const float*)d_in[0];
    const float* W    = (const float*)d_in[1];
    const float* attS = (const float*)d_in[2];
    const float* attD = (const float*)d_in[3];
    const float* bias = (const float*)d_in[4];
    const int*   ei   = (const int*)d_in[5];

    int n = in_sizes[0] / FH;        // 50000
    int E = in_sizes[5] / 2;         // 800000
    const int* src = ei;
    const int* dst = ei + E;

    int nhist = (E + 255) / 256;                 // 3125
    int nscan = (n + 255) / 256;                 // 196

    // host-side resources, created once (host objects only; no device memory)
    static cudaStream_t s_side = nullptr;
    static cudaEvent_t  ev_fork = nullptr, ev_att = nullptr, ev_xp = nullptr;
    if (s_side == nullptr) {
        cudaStreamCreateWithFlags(&s_side, cudaStreamNonBlocking);
        cudaEventCreateWithFlags(&ev_fork, cudaEventDisableTiming);
        cudaEventCreateWithFlags(&ev_att, cudaEventDisableTiming);
        cudaEventCreateWithFlags(&ev_xp, cudaEventDisableTiming);
    }

    // side stream: attention halves first (small), then the big projection
    cudaEventRecord(ev_fork, 0);
    cudaStreamWaitEvent(s_side, ev_fork, 0);
    k_att<<<(n + 255) / 256, 256, 0, s_side>>>(x, W, attS, attD, n);
    cudaEventRecord(ev_att, s_side);
    k_gemm<<<(n + 127) / 128, 512, 0, s_side>>>(x, W, n);
    cudaEventRecord(ev_xp, s_side);

    // main stream: hist+scan (independent), then scatter+weights (needs k_att)
    k_hs<<<nhist + nscan, 256>>>(dst, n, E, nhist, nscan);
    cudaStreamWaitEvent(0, ev_att, 0);
    k_scatw<<<(E + n + 255) / 256, 256>>>(src, dst, E, n);

    // aggregation needs xp -> join on the big GEMM
    cudaStreamWaitEvent(0, ev_xp, 0);
    k_agg<<<(n * 32 + 255) / 256, 256>>>(bias, (float*)d_out, n);
}